// round 6
// baseline (speedup 1.0000x reference)
#include <cuda_runtime.h>
#include <math.h>

#define BB 64
#define TT 512
#define EE 256
#define HH 512
#define G4 2048            // 4*H
#define NB 128             // persistent scan blocks: 64 j-slices x 2 batch-halves

#define OUT_HT_OFF  16777216ull           // B*T*H
#define OUT_CT_OFF  16809984ull           // + B*H
#define OUT_MASK_OFF 16842752ull          // + B*H

// -------- device scratch (no allocations allowed) --------
__device__ float g_gates[(size_t)TT * G4 * BB];   // 256 MB: [t][g][b]
__device__ float g_hbuf[2][HH * BB];              // double-buffered h, layout [j][b]
__device__ unsigned g_bar_count;
__device__ unsigned g_bar_phase;

// -------- packed f32x2 helpers --------
struct __align__(16) U64x2 { unsigned long long lo, hi; };

__device__ __forceinline__ void fma2(unsigned long long &d, unsigned long long a, unsigned long long b) {
    asm("fma.rn.f32x2 %0, %1, %2, %0;" : "+l"(d) : "l"(a), "l"(b));
}
__device__ __forceinline__ void add2(unsigned long long &d, unsigned long long a) {
    asm("add.rn.f32x2 %0, %0, %1;" : "+l"(d) : "l"(a));
}
__device__ __forceinline__ unsigned long long splat2(float x) {
    unsigned long long r; asm("mov.b64 %0, {%1, %1};" : "=l"(r) : "f"(x)); return r;
}
__device__ __forceinline__ unsigned long long pk2(float a, float b) {
    unsigned long long r; asm("mov.b64 %0, {%1, %2};" : "=l"(r) : "f"(a), "f"(b)); return r;
}
__device__ __forceinline__ float2 unpk2(unsigned long long v) {
    float2 r; asm("mov.b64 {%0, %1}, %2;" : "=f"(r.x), "=f"(r.y) : "l"(v)); return r;
}
__device__ __forceinline__ void cp16(void* d, const void* s) {
    unsigned sa = (unsigned)__cvta_generic_to_shared(d);
    asm volatile("cp.async.cg.shared.global [%0], [%1], 16;" :: "r"(sa), "l"(s) : "memory");
}
__device__ __forceinline__ void cp_commit_wait() {
    asm volatile("cp.async.commit_group;\n\tcp.async.wait_group 0;" ::: "memory");
}

__device__ __forceinline__ float sigf(float x) {
    float e = __expf(-x);
    return __fdividef(1.0f, 1.0f + e);
}
__device__ __forceinline__ float tanhf_fast(float x) {
    float e = __expf(2.0f * x);
    return 1.0f - __fdividef(2.0f, e + 1.0f);
}

// -------- reset kernel --------
__global__ void reset_kernel() {
    int idx = blockIdx.x * blockDim.x + threadIdx.x;
    if (idx == 0) { g_bar_count = 0u; g_bar_phase = 0u; }
    if (idx < HH * BB) {
        g_hbuf[0][idx] = 0.f;
        g_hbuf[1][idx] = 0.f;
    }
}

// -------- mask kernel --------
__global__ void mask_kernel(const int* __restrict__ lengths, float* __restrict__ out_mask) {
    int t = threadIdx.x;
    int b = blockIdx.x;
    out_mask[(size_t)b * TT + t] = (t < lengths[b]) ? 1.0f : 0.0f;
}

// -------- gates_x GEMM (f32x2, gate-pair packed) --------
// grid: (16 g-tiles of 128, 512 t), 256 threads, thread = 8 gates x 4 batches.
__global__ __launch_bounds__(256) void gates_kernel(
    const int* __restrict__ inputs, const float* __restrict__ emb,
    const float* __restrict__ W_ih, const float* __restrict__ b_ih,
    const float* __restrict__ b_hh)
{
    __shared__ float xs[BB][33];      // [b][kk]
    __shared__ float Ws[32][132];     // [kk][g], 128 used + pad
    __shared__ int   ts[BB];

    const int t  = blockIdx.y;
    const int g0 = blockIdx.x * 128;
    const int tid = threadIdx.x;

    if (tid < BB) ts[tid] = inputs[(size_t)tid * TT + t];
    __syncthreads();

    const int bq = tid & 15;        // 16 batch groups (4 b each)
    const int gq = tid >> 4;        // 16 gate groups (8 g each)
    const int lk = tid & 31;        // loader lane (kk)
    const int ls = tid >> 5;        // loader row sub

    unsigned long long acc[4][4];   // [gate-pair][batch], each = 2 gates
#pragma unroll
    for (int p = 0; p < 4; p++)
#pragma unroll
        for (int i = 0; i < 4; i++) acc[p][i] = 0ull;

    for (int kc = 0; kc < EE; kc += 32) {
#pragma unroll
        for (int bp = 0; bp < 8; bp++) {
            int b = ls + bp * 8;
            xs[b][lk] = emb[(size_t)ts[b] * EE + kc + lk];
        }
#pragma unroll
        for (int gp = 0; gp < 16; gp++) {
            int g = ls + gp * 8;
            Ws[lk][g] = W_ih[(size_t)(g0 + g) * EE + kc + lk];
        }
        __syncthreads();

#pragma unroll
        for (int kk = 0; kk < 32; kk++) {
            unsigned long long sx0 = splat2(xs[4 * bq + 0][kk]);
            unsigned long long sx1 = splat2(xs[4 * bq + 1][kk]);
            unsigned long long sx2 = splat2(xs[4 * bq + 2][kk]);
            unsigned long long sx3 = splat2(xs[4 * bq + 3][kk]);
            U64x2 wA = *(const U64x2*)&Ws[kk][8 * gq];      // gates 0..3 of slice
            U64x2 wB = *(const U64x2*)&Ws[kk][8 * gq + 4];  // gates 4..7
            fma2(acc[0][0], wA.lo, sx0); fma2(acc[0][1], wA.lo, sx1);
            fma2(acc[0][2], wA.lo, sx2); fma2(acc[0][3], wA.lo, sx3);
            fma2(acc[1][0], wA.hi, sx0); fma2(acc[1][1], wA.hi, sx1);
            fma2(acc[1][2], wA.hi, sx2); fma2(acc[1][3], wA.hi, sx3);
            fma2(acc[2][0], wB.lo, sx0); fma2(acc[2][1], wB.lo, sx1);
            fma2(acc[2][2], wB.lo, sx2); fma2(acc[2][3], wB.lo, sx3);
            fma2(acc[3][0], wB.hi, sx0); fma2(acc[3][1], wB.hi, sx1);
            fma2(acc[3][2], wB.hi, sx2); fma2(acc[3][3], wB.hi, sx3);
        }
        __syncthreads();
    }

    const size_t tbase = (size_t)t * ((size_t)G4 * BB);
#pragma unroll
    for (int p = 0; p < 4; p++) {
        int ga = g0 + 8 * gq + 2 * p;
        float biasa = b_ih[ga] + b_hh[ga];
        float biasb = b_ih[ga + 1] + b_hh[ga + 1];
        float2 v0 = unpk2(acc[p][0]);
        float2 v1 = unpk2(acc[p][1]);
        float2 v2 = unpk2(acc[p][2]);
        float2 v3 = unpk2(acc[p][3]);
        float4 ra = make_float4(v0.x + biasa, v1.x + biasa, v2.x + biasa, v3.x + biasa);
        float4 rb = make_float4(v0.y + biasb, v1.y + biasb, v2.y + biasb, v3.y + biasb);
        *(float4*)&g_gates[tbase + (size_t)ga * BB + 4 * bq] = ra;
        *(float4*)&g_gates[tbase + (size_t)(ga + 1) * BB + 4 * bq] = rb;
    }
}

// -------- grid-wide barrier --------
__device__ __forceinline__ void grid_barrier(unsigned target, unsigned nb) {
    __syncthreads();
    if (threadIdx.x == 0) {
        __threadfence();
        unsigned prev = atomicAdd(&g_bar_count, 1u);
        if (prev == nb - 1u) {
            atomicExch(&g_bar_count, 0u);
            __threadfence();
            atomicExch(&g_bar_phase, target);
        } else {
            while (*((volatile unsigned*)&g_bar_phase) < target) { }
            __threadfence();
        }
    }
    __syncthreads();
}

// -------- persistent LSTM scan (f32x2) --------
// 128 blocks = 64 j-slices x 2 batch-halves, 256 threads.
// Block owns 8 hidden units (j0..j0+7) for 32 batches (bh*32..+31).
// Thread = (kq half of K, jp j-pair, lane=(jhalf,bp)): 1 j x 4 gates x 256 k x 2 batches.
__global__ __launch_bounds__(256, 1) void scan_kernel(
    const int* __restrict__ lengths, const int* __restrict__ reset_idx,
    const float* __restrict__ W_hh, float* __restrict__ out)
{
    extern __shared__ float sm[];
    float* h_s = sm;                                              // 512*32 floats = 64KB
    unsigned long long* Wd = (unsigned long long*)(sm + 512 * 32); // 512*32 ull = 128KB (dup'd W)
    unsigned long long* red = Wd + 512 * 32;                       // 1024 ull = 8KB

    const int tid  = threadIdx.x;
    const int lane = tid & 31;
    const int wid  = tid >> 5;
    const int kq   = wid >> 2;          // 0..1 (K half)
    const int jp   = wid & 3;           // 0..3 (j-pair)
    const int bp   = lane & 15;         // 0..15 (batch-pair)
    const int jhalf = lane >> 4;        // 0..1
    const int jj   = jp * 2 + jhalf;    // 0..7 local j
    const int jblk = blockIdx.x >> 1;
    const int bh   = blockIdx.x & 1;
    const int j0   = jblk * 8;

    // Preload duplicated W slice: Wd[k*32 + (jl*4+g)] = splat(W_hh[g*H + j0+jl][k])
    for (int i = tid; i < 32 * HH; i += 256) {
        int r = i >> 9;                 // 0..31
        int k = i & (HH - 1);
        int g = r & 3, jl = r >> 2;
        Wd[(size_t)k * 32 + r] = splat2(W_hh[(size_t)(g * HH + j0 + jl) * HH + k]);
    }

    // cell threads: tid < 128, each finalizes 2 cells
    const bool is_cell = (tid < 128);
    const int cjj = tid >> 4;           // 0..7
    const int cbp = tid & 15;           // 0..15
    const int cj  = j0 + cjj;
    const int b0  = bh * 32 + 2 * cbp;
    const int b1  = b0 + 1;
    int len0 = 0, len1 = 0;
    if (is_cell) { len0 = lengths[b0]; len1 = lengths[b1]; }
    float hp0 = 0.f, hp1 = 0.f, cp0 = 0.f, cp1 = 0.f;

    __syncthreads();

    const int kbase = kq * 256;
    const size_t gx_stride = (size_t)G4 * BB;
    const float* gxp0 = g_gates + (size_t)(0 * HH + cj) * BB + b0;
    const float* gxp1 = g_gates + (size_t)(1 * HH + cj) * BB + b0;
    const float* gxp2 = g_gates + (size_t)(2 * HH + cj) * BB + b0;
    const float* gxp3 = g_gates + (size_t)(3 * HH + cj) * BB + b0;

    for (int t = 0; t < TT; t++) {
        // prefetch gate pre-activations + reset flags (overlaps with copy + dot)
        unsigned long long gx0 = 0, gx1 = 0, gx2 = 0, gx3 = 0;
        int r0 = 0, r1 = 0;
        if (is_cell) {
            size_t off = (size_t)t * gx_stride;
            gx0 = *(const unsigned long long*)(gxp0 + off);
            gx1 = *(const unsigned long long*)(gxp1 + off);
            gx2 = *(const unsigned long long*)(gxp2 + off);
            gx3 = *(const unsigned long long*)(gxp3 + off);
            r0 = reset_idx[(size_t)b0 * TT + t];
            r1 = reset_idx[(size_t)b1 * TT + t];
        }

        // async copy h tile (this block's 32 batches): 4096 float4 over 256 threads
        {
            const float4* src = (const float4*)(g_hbuf[t & 1]);
            float4* dst = (float4*)h_s;
#pragma unroll
            for (int i = 0; i < 16; i++) {
                int idx = tid + i * 256;
                int k = idx >> 3, b4 = idx & 7;
                cp16(dst + (size_t)k * 8 + b4, src + (size_t)k * 16 + bh * 8 + b4);
            }
            cp_commit_wait();
        }
        __syncthreads();

        // 4 gate dots over this thread's 256-k half
        unsigned long long a0 = 0ull, a1 = 0ull, a2 = 0ull, a3 = 0ull;
#pragma unroll 8
        for (int kk = 0; kk < 256; kk++) {
            int k = kbase + kk;
            unsigned long long hv = *(const unsigned long long*)(h_s + (size_t)k * 32 + 2 * bp);
            const U64x2* W2 = (const U64x2*)(Wd + (size_t)k * 32 + jj * 4);
            U64x2 wa = W2[0];   // gates 0,1
            U64x2 wb = W2[1];   // gates 2,3
            fma2(a0, hv, wa.lo);
            fma2(a1, hv, wa.hi);
            fma2(a2, hv, wb.lo);
            fma2(a3, hv, wb.hi);
        }
        // store partials: red[((kq*8+jj)*4+g)*16 + bp]
        {
            unsigned long long* rp = red + ((size_t)(kq * 8 + jj) * 4) * 16 + bp;
            rp[0 * 16] = a0; rp[1 * 16] = a1; rp[2 * 16] = a2; rp[3 * 16] = a3;
        }
        __syncthreads();

        if (is_cell) {
            const unsigned long long* rA = red + ((size_t)(0 * 8 + cjj) * 4) * 16 + cbp;
            const unsigned long long* rB = red + ((size_t)(1 * 8 + cjj) * 4) * 16 + cbp;
            add2(gx0, rA[0 * 16]); add2(gx0, rB[0 * 16]);
            add2(gx1, rA[1 * 16]); add2(gx1, rB[1 * 16]);
            add2(gx2, rA[2 * 16]); add2(gx2, rB[2 * 16]);
            add2(gx3, rA[3 * 16]); add2(gx3, rB[3 * 16]);
            float2 ai = unpk2(gx0), af = unpk2(gx1), ag = unpk2(gx2), ao = unpk2(gx3);

            // batch 0
            float i0 = sigf(ai.x), f0 = sigf(af.x), g0v = tanhf_fast(ag.x), o0 = sigf(ao.x);
            float cn0 = fmaf(f0, cp0, i0 * g0v);
            float hn0 = o0 * tanhf_fast(cn0);
            bool m0 = (t < len0);
            float hx0 = m0 ? hn0 : hp0;
            float cx0 = m0 ? cn0 : cp0;
            // batch 1
            float i1 = sigf(ai.y), f1 = sigf(af.y), g1v = tanhf_fast(ag.y), o1 = sigf(ao.y);
            float cn1 = fmaf(f1, cp1, i1 * g1v);
            float hn1 = o1 * tanhf_fast(cn1);
            bool m1 = (t < len1);
            float hx1 = m1 ? hn1 : hp1;
            float cx1 = m1 ? cn1 : cp1;

            out[(size_t)b0 * (TT * HH) + (size_t)t * HH + cj] = hx0;
            out[(size_t)b1 * (TT * HH) + (size_t)t * HH + cj] = hx1;

            hp0 = r0 ? 0.f : hx0;  cp0 = r0 ? 0.f : cx0;
            hp1 = r1 ? 0.f : hx1;  cp1 = r1 ? 0.f : cx1;

            *(unsigned long long*)&g_hbuf[(t + 1) & 1][(size_t)cj * BB + b0] = pk2(hp0, hp1);

            if (t == TT - 1) {
                out[OUT_HT_OFF + (size_t)b0 * HH + cj] = hp0;
                out[OUT_HT_OFF + (size_t)b1 * HH + cj] = hp1;
                out[OUT_CT_OFF + (size_t)b0 * HH + cj] = cp0;
                out[OUT_CT_OFF + (size_t)b1 * HH + cj] = cp1;
            }
        }

        if (t < TT - 1) grid_barrier((unsigned)(t + 1), (unsigned)gridDim.x);
    }
}

extern "C" void kernel_launch(void* const* d_in, const int* in_sizes, int n_in,
                              void* d_out, int out_size) {
    const int*   inputs    = (const int*)d_in[0];
    const int*   lengths   = (const int*)d_in[1];
    const int*   reset_idx = (const int*)d_in[2];
    const float* emb       = (const float*)d_in[3];
    const float* W_ih      = (const float*)d_in[4];
    const float* W_hh      = (const float*)d_in[5];
    const float* b_ih      = (const float*)d_in[6];
    const float* b_hh      = (const float*)d_in[7];
    float* out = (float*)d_out;

    // h_s 64KB + Wd 128KB + red 8KB = 200KB
    const int smem_scan = (512 * 32) * 4 + (512 * 32) * 8 + 1024 * 8;
    cudaFuncSetAttribute(scan_kernel, cudaFuncAttributeMaxDynamicSharedMemorySize, smem_scan);

    reset_kernel<<<128, 256>>>();
    gates_kernel<<<dim3(16, 512), 256>>>(inputs, emb, W_ih, b_ih, b_hh);
    mask_kernel<<<BB, TT>>>(lengths, out + OUT_MASK_OFF);
    scan_kernel<<<NB, 256, smem_scan>>>(lengths, reset_idx, W_hh, out);
}